// round 16
// baseline (speedup 1.0000x reference)
#include <cuda_runtime.h>
#include <cuda_bf16.h>
#include <cstdint>

#define T_STEPS 32768
#define H 1024
#define NB 64          // recurrence blocks (one per SM)
#define RPB 16         // hidden rows per block
#define NT 640         // 16 compute warps (512) + 4 poller warps (128)
#define NCOMP 512
#define NCHUNK 256     // 32768 / 128 m-chunks of g_c
#define NGB 2048       // gemm blocks (256 m-chunks x 8 n-chunks)

// ---------------- device scratch (static, no allocations) ----------------
__device__ float g_c[(size_t)T_STEPS * H];          // x_t @ W_x^T + b (128 MB)
__device__ unsigned long long g_hp[2][H];           // packed (tag<<32 | h-bits)
__device__ float g_hfin[H];                         // final h_T
__device__ int   g_cnt[NCHUNK];                     // per-m-chunk completion counters

__device__ __forceinline__ void ld_pair2(const unsigned long long* p,
                                         unsigned long long& a, unsigned long long& b) {
    asm volatile("ld.volatile.global.v2.u64 {%0,%1}, [%2];"
                 : "=l"(a), "=l"(b) : "l"(p) : "memory");
}
__device__ __forceinline__ void st_pair(unsigned long long* p, unsigned long long v) {
    asm volatile("st.relaxed.gpu.global.b64 [%0], %1;" :: "l"(p), "l"(v) : "memory");
}
__device__ __forceinline__ unsigned long long pack_pair(int tag, float val) {
    return ((unsigned long long)(unsigned)tag << 32) | (unsigned long long)__float_as_uint(val);
}
__device__ __forceinline__ int   pair_tag(unsigned long long v) { return (int)(v >> 32); }
__device__ __forceinline__ float pair_val(unsigned long long v) { return __uint_as_float((unsigned)v); }
__device__ __forceinline__ int ld_acq(const int* p) {
    int v;
    asm volatile("ld.acquire.gpu.global.s32 %0, [%1];" : "=r"(v) : "l"(p) : "memory");
    return v;
}

// ---------------- init (graph-replay safe) ----------------
__global__ void init_a() {   // buf0: h_0 = 0, tag 0
    int i = blockIdx.x * blockDim.x + threadIdx.x;
    if (i < H) g_hp[0][i] = pack_pair(0, 0.0f);
}
__global__ void init_b() {   // buf1: poisoned tag -1
    int i = blockIdx.x * blockDim.x + threadIdx.x;
    if (i < H) g_hp[1][i] = pack_pair(-1, 0.0f);
}
__global__ void init_c() {   // gemm chunk counters
    int i = blockIdx.x * blockDim.x + threadIdx.x;
    if (i < NCHUNK) g_cnt[i] = 0;
}

// ---------------- fast tanh: 1 - 2/(exp(2x)+1), inf-safe -----------------
__device__ __forceinline__ float tanh_fast(float x) {
    float e = __expf(2.f * x);
    return 1.f - 2.f / (e + 1.f);
}

// ---------------- fused kernel ----------------
// Blocks 0..63   : persistent recurrence (pollers + chunked dataflow dot).
// Blocks 64..2111: GEMM producer for g_c tile, bumps g_cnt when done.
#define GBM 128
#define GBN 128
#define GBK 8

__global__ void __launch_bounds__(NT) rnn_fused(const float* __restrict__ x,
                                                const float* __restrict__ W_i2h,
                                                const float* __restrict__ b_i2h) {
    __shared__ float sbuf[2 * H];                   // rnn: sh[2][1024] | gemm: As+Bs
    __shared__ unsigned long long spair[RPB];       // rnn: fresh packed pairs
    __shared__ int sflag[2][8];                     // rnn: per-chunk freshness flags

    int tid = threadIdx.x;
    int bid = blockIdx.x;

    if (bid >= NB) {
        // ================= GEMM producer role =================
        float (*As)[GBM] = (float (*)[GBM])(sbuf);
        float (*Bs)[GBN] = (float (*)[GBN])(sbuf + GBK * GBM);
        int g  = bid - NB;
        int m0 = (g >> 3) * GBM;
        int n0 = (g & 7) * GBN;

        float acc[8][8];
        float4 a, bv;
        const float* xg = nullptr;
        const float* wg = nullptr;
        int lr = 0, lc = 0, tx = 0, ty = 0;
        if (tid < 256) {
            lr = tid >> 1;
            lc = (tid & 1) * 4;
            xg = x + (size_t)(m0 + lr) * 1024 + lc;
            wg = W_i2h + (size_t)(n0 + lr) * 2048 + lc;   // W_x = cols [0,1024)
            tx = tid & 15; ty = tid >> 4;
#pragma unroll
            for (int i = 0; i < 8; i++)
#pragma unroll
                for (int j = 0; j < 8; j++) acc[i][j] = 0.f;
            a  = *(const float4*)xg;
            bv = *(const float4*)wg;
        }

        for (int k0 = 0; k0 < 1024; k0 += GBK) {
            __syncthreads();
            if (tid < 256) {
                As[lc + 0][lr] = a.x;  As[lc + 1][lr] = a.y;
                As[lc + 2][lr] = a.z;  As[lc + 3][lr] = a.w;
                Bs[lc + 0][lr] = bv.x; Bs[lc + 1][lr] = bv.y;
                Bs[lc + 2][lr] = bv.z; Bs[lc + 3][lr] = bv.w;
            }
            __syncthreads();
            if (tid < 256) {
                if (k0 + GBK < 1024) {
                    a  = *(const float4*)(xg + k0 + GBK);
                    bv = *(const float4*)(wg + k0 + GBK);
                }
#pragma unroll
                for (int k = 0; k < GBK; k++) {
                    float ar[8], br[8];
                    *(float4*)(ar)     = *(const float4*)&As[k][ty * 8];
                    *(float4*)(ar + 4) = *(const float4*)&As[k][ty * 8 + 4];
                    *(float4*)(br)     = *(const float4*)&Bs[k][tx * 8];
                    *(float4*)(br + 4) = *(const float4*)&Bs[k][tx * 8 + 4];
#pragma unroll
                    for (int i = 0; i < 8; i++)
#pragma unroll
                        for (int j = 0; j < 8; j++) acc[i][j] += ar[i] * br[j];
                }
            }
        }

        if (tid < 256) {
            float bias[8];
#pragma unroll
            for (int j = 0; j < 8; j++) bias[j] = __ldg(b_i2h + n0 + tx * 8 + j);
#pragma unroll
            for (int i = 0; i < 8; i++) {
                float4 v0 = make_float4(acc[i][0] + bias[0], acc[i][1] + bias[1],
                                        acc[i][2] + bias[2], acc[i][3] + bias[3]);
                float4 v1 = make_float4(acc[i][4] + bias[4], acc[i][5] + bias[5],
                                        acc[i][6] + bias[6], acc[i][7] + bias[7]);
                float* cp = g_c + (size_t)(m0 + ty * 8 + i) * 1024 + n0 + tx * 8;
                *(float4*)(cp)     = v0;
                *(float4*)(cp + 4) = v1;
            }
        }
        __threadfence();
        __syncthreads();
        if (tid == 0) atomicAdd(&g_cnt[g >> 3], 1);   // 8 => chunk ready
        return;
    }

    // ================= recurrence role =================
    float (*sh)[H] = (float (*)[H])sbuf;            // double-buffered staged h_t

    int b  = bid;
    int r0 = b * RPB;

    if (tid < 16) {                                  // one-time flag init
        sflag[tid >> 3][tid & 7] = -1;
    }
    __syncthreads();                                 // all 640 threads, once

    if (tid < NCOMP) {
        // ---------------- compute warp: row r0+w ----------------
        int w = tid >> 5;
        int L = tid & 31;
        int row = r0 + w;

        float4 wv[8];
        {
            const float* wp = W_i2h + (size_t)row * 2048 + 1024 + 4 * L;
#pragma unroll
            for (int j = 0; j < 8; j++) wv[j] = *(const float4*)(wp + 128 * j);
        }

        float cnext = 0.f;
        if (L == 0) {
            while (ld_acq(&g_cnt[0]) < 8) {}
            cnext = __ldg(g_c + row);
        }

        const int sbase = 4 * L;

        for (int t = 0; t < T_STEPS; t++) {
            float ccur = cnext;
            if (L == 0 && t + 1 < T_STEPS) {
                int tn = t + 1;
                if ((tn & 127) == 0) {
                    const int* cp = &g_cnt[tn >> 7];
                    while (ld_acq(cp) < 8) {}
                }
                cnext = __ldg(g_c + (size_t)tn * H + row);
            }

            // chunked dataflow dot: spin cheap smem flag per 128-k chunk
            const float* shb = sh[t & 1];
            volatile int* fl = sflag[t & 1];
            float a0 = 0.f, a1 = 0.f, a2 = 0.f, a3 = 0.f;
#pragma unroll
            for (int j = 0; j < 8; j += 4) {
                while (fl[j + 0] < t) {}
                asm volatile("" ::: "memory");
                float4 h0 = *(const float4*)&shb[sbase + 128 * (j + 0)];
                a0 += wv[j + 0].x * h0.x + wv[j + 0].y * h0.y + wv[j + 0].z * h0.z + wv[j + 0].w * h0.w;
                while (fl[j + 1] < t) {}
                asm volatile("" ::: "memory");
                float4 h1 = *(const float4*)&shb[sbase + 128 * (j + 1)];
                a1 += wv[j + 1].x * h1.x + wv[j + 1].y * h1.y + wv[j + 1].z * h1.z + wv[j + 1].w * h1.w;
                while (fl[j + 2] < t) {}
                asm volatile("" ::: "memory");
                float4 h2 = *(const float4*)&shb[sbase + 128 * (j + 2)];
                a2 += wv[j + 2].x * h2.x + wv[j + 2].y * h2.y + wv[j + 2].z * h2.z + wv[j + 2].w * h2.w;
                while (fl[j + 3] < t) {}
                asm volatile("" ::: "memory");
                float4 h3 = *(const float4*)&shb[sbase + 128 * (j + 3)];
                a3 += wv[j + 3].x * h3.x + wv[j + 3].y * h3.y + wv[j + 3].z * h3.z + wv[j + 3].w * h3.w;
            }
            float acc = (a0 + a1) + (a2 + a3);
#pragma unroll
            for (int off = 16; off > 0; off >>= 1)
                acc += __shfl_down_sync(0xffffffffu, acc, off);

            if (L == 0) {
                float hn = tanh_fast(acc + ccur);
                spair[w] = pack_pair(t + 1, hn);
                if (t == T_STEPS - 1) g_hfin[row] = hn;
            }
            asm volatile("bar.sync 1, %0;" :: "n"(NCOMP) : "memory");   // compute-only

            // publish: warp0 lanes<16, coalesced 128B line
            if (w == 0 && L < RPB)
                st_pair(&g_hp[(t + 1) & 1][r0 + L], spair[L]);
        }
    } else {
        // ---------------- poller warp: 8 pairs per thread ----------------
        int q  = tid - NCOMP;          // 0..127
        int e0 = 8 * q;                // first pair index (h element)
        int j  = q >> 4;               // chunk id (16 threads per chunk)
        // half-warp group mask within this poller warp
        unsigned int gmask = ((q & 16) ? 0xFFFF0000u : 0x0000FFFFu);

        for (int t = 0; t < T_STEPS; t++) {
            const unsigned long long* p = &g_hp[t & 1][e0];
            unsigned long long x0, x1, x2, x3, x4, x5, x6, x7;
            for (;;) {
                ld_pair2(p + 0, x0, x1);
                ld_pair2(p + 2, x2, x3);
                ld_pair2(p + 4, x4, x5);
                ld_pair2(p + 6, x6, x7);
                int m = pair_tag(x0); m = min(m, pair_tag(x1));
                m = min(m, pair_tag(x2)); m = min(m, pair_tag(x3));
                m = min(m, pair_tag(x4)); m = min(m, pair_tag(x5));
                m = min(m, pair_tag(x6)); m = min(m, pair_tag(x7));
                if (m >= t) break;
            }
            float4* dst = (float4*)&sh[t & 1][e0];
            dst[0] = make_float4(pair_val(x0), pair_val(x1), pair_val(x2), pair_val(x3));
            dst[1] = make_float4(pair_val(x4), pair_val(x5), pair_val(x6), pair_val(x7));
            __syncwarp(gmask);                       // group staged + mem ordering
            if ((q & 15) == 0)
                ((volatile int*)sflag[t & 1])[j] = t;
        }
    }
}

// ---------------- output: out[r] = h_T . W_h2o[r] + b_h2o[r] -------------
__global__ void __launch_bounds__(256) out_kernel(const float* __restrict__ W_h2o,
                                                  const float* __restrict__ b_h2o,
                                                  float* __restrict__ out) {
    int r = blockIdx.x * 8 + (threadIdx.x >> 5);
    int lane = threadIdx.x & 31;
    const float* wr = W_h2o + (size_t)r * 1024;
    const float* h  = g_hfin;
    float acc = 0.f;
    for (int k4 = lane; k4 < 256; k4 += 32) {
        float4 wvv = *(const float4*)(wr + k4 * 4);
        float4 hv  = *(const float4*)(h + k4 * 4);
        acc += wvv.x * hv.x + wvv.y * hv.y + wvv.z * hv.z + wvv.w * hv.w;
    }
#pragma unroll
    for (int off = 16; off > 0; off >>= 1)
        acc += __shfl_down_sync(0xffffffffu, acc, off);
    if (lane == 0) out[r] = acc + __ldg(b_h2o + r);
}

// ---------------- launch (5 launches: fused sits in ncu capture slot) ----
extern "C" void kernel_launch(void* const* d_in, const int* in_sizes, int n_in,
                              void* d_out, int out_size) {
    const float* x      = (const float*)d_in[0];
    const float* W_i2h  = (const float*)d_in[1];
    const float* b_i2h  = (const float*)d_in[2];
    const float* W_h2o  = (const float*)d_in[3];
    const float* b_h2o  = (const float*)d_in[4];
    float* out = (float*)d_out;

    init_a<<<2, 512>>>();
    init_b<<<2, 512>>>();
    init_c<<<1, 256>>>();
    rnn_fused<<<NB + NGB, NT>>>(x, W_i2h, b_i2h);
    out_kernel<<<H / 8, 256>>>(W_h2o, b_h2o, out);
}

// round 17
// speedup vs baseline: 1.5384x; 1.5384x over previous
#include <cuda_runtime.h>
#include <cuda_bf16.h>
#include <cstdint>

#define T_STEPS 32768
#define H 1024
#define NB 64          // recurrence blocks (one per SM)
#define RPB 16         // hidden rows per block
#define NT 512         // threads per block
#define NCHUNK 256     // 32768 / 128 m-chunks
#define NGB 2048       // gemm blocks (256 m-chunks x 8 n-chunks)

// ---------------- device scratch (static, no allocations) ----------------
__device__ float g_c[(size_t)T_STEPS * H];          // x_t @ W_x^T + b (128 MB)
__device__ unsigned long long g_hp[2][H];           // packed (tag<<32 | h-bits)
__device__ float g_hfin[H];                         // final h_T
__device__ int   g_cnt[NCHUNK];                     // per-m-chunk completion counters

__device__ __forceinline__ void ld_pair2(const unsigned long long* p,
                                         unsigned long long& a, unsigned long long& b) {
    asm volatile("ld.volatile.global.v2.u64 {%0,%1}, [%2];"
                 : "=l"(a), "=l"(b) : "l"(p) : "memory");
}
__device__ __forceinline__ void st_pair(unsigned long long* p, unsigned long long v) {
    asm volatile("st.relaxed.gpu.global.b64 [%0], %1;" :: "l"(p), "l"(v) : "memory");
}
__device__ __forceinline__ unsigned long long pack_pair(int tag, float val) {
    return ((unsigned long long)(unsigned)tag << 32) | (unsigned long long)__float_as_uint(val);
}
__device__ __forceinline__ int   pair_tag(unsigned long long v) { return (int)(v >> 32); }
__device__ __forceinline__ float pair_val(unsigned long long v) { return __uint_as_float((unsigned)v); }
__device__ __forceinline__ int ld_acq(const int* p) {
    int v;
    asm volatile("ld.acquire.gpu.global.s32 %0, [%1];" : "=r"(v) : "l"(p) : "memory");
    return v;
}

// ---------------- init (graph-replay safe) ----------------
__global__ void init_a() {   // buf0: h_0 = 0, tag 0
    int i = blockIdx.x * blockDim.x + threadIdx.x;
    if (i < H) g_hp[0][i] = pack_pair(0, 0.0f);
}
__global__ void init_b() {   // buf1: poisoned tag -1
    int i = blockIdx.x * blockDim.x + threadIdx.x;
    if (i < H) g_hp[1][i] = pack_pair(-1, 0.0f);
}
__global__ void init_c() {   // gemm chunk counters
    int i = blockIdx.x * blockDim.x + threadIdx.x;
    if (i < NCHUNK) g_cnt[i] = 0;
}

// ---------------- fast tanh: 1 - 2/(exp(2x)+1), inf-safe -----------------
__device__ __forceinline__ float tanh_fast(float x) {
    float e = __expf(2.f * x);
    return 1.f - 2.f / (e + 1.f);
}

// ---------------- fused kernel ----------------
// Blocks 0..63   : persistent recurrence (R15 protocol, pipelined polling).
// Blocks 64..2111: GEMM producer; block g=b-64 computes tile
//                  m=[128*(g>>3)), n=[128*(g&7)) of g_c, then bumps g_cnt.
#define GBM 128
#define GBN 128
#define GBK 8

__global__ void __launch_bounds__(NT) rnn_fused(const float* __restrict__ x,
                                                const float* __restrict__ W_i2h,
                                                const float* __restrict__ b_i2h) {
    __shared__ float sbuf[2 * H];                 // rnn: sh[2][1024] | gemm: As+Bs
    __shared__ float sw[RPB];                     // rnn: per-warp row sums

    int tid = threadIdx.x;
    int bid = blockIdx.x;

    if (bid >= NB) {
        // ================= GEMM producer role =================
        float (*As)[GBM] = (float (*)[GBM])(sbuf);
        float (*Bs)[GBN] = (float (*)[GBN])(sbuf + GBK * GBM);
        int g  = bid - NB;
        int m0 = (g >> 3) * GBM;
        int n0 = (g & 7) * GBN;

        float acc[8][8];
        float4 a, bv;
        const float* xg = nullptr;
        const float* wg = nullptr;
        int lr = 0, lc = 0, tx = 0, ty = 0;
        if (tid < 256) {
            lr = tid >> 1;
            lc = (tid & 1) * 4;
            xg = x + (size_t)(m0 + lr) * 1024 + lc;
            wg = W_i2h + (size_t)(n0 + lr) * 2048 + lc;   // W_x = cols [0,1024)
            tx = tid & 15; ty = tid >> 4;
#pragma unroll
            for (int i = 0; i < 8; i++)
#pragma unroll
                for (int j = 0; j < 8; j++) acc[i][j] = 0.f;
            a  = *(const float4*)xg;
            bv = *(const float4*)wg;
        }

        for (int k0 = 0; k0 < 1024; k0 += GBK) {
            __syncthreads();
            if (tid < 256) {
                As[lc + 0][lr] = a.x;  As[lc + 1][lr] = a.y;
                As[lc + 2][lr] = a.z;  As[lc + 3][lr] = a.w;
                Bs[lc + 0][lr] = bv.x; Bs[lc + 1][lr] = bv.y;
                Bs[lc + 2][lr] = bv.z; Bs[lc + 3][lr] = bv.w;
            }
            __syncthreads();
            if (tid < 256) {
                if (k0 + GBK < 1024) {
                    a  = *(const float4*)(xg + k0 + GBK);
                    bv = *(const float4*)(wg + k0 + GBK);
                }
#pragma unroll
                for (int k = 0; k < GBK; k++) {
                    float ar[8], br[8];
                    *(float4*)(ar)     = *(const float4*)&As[k][ty * 8];
                    *(float4*)(ar + 4) = *(const float4*)&As[k][ty * 8 + 4];
                    *(float4*)(br)     = *(const float4*)&Bs[k][tx * 8];
                    *(float4*)(br + 4) = *(const float4*)&Bs[k][tx * 8 + 4];
#pragma unroll
                    for (int i = 0; i < 8; i++)
#pragma unroll
                        for (int j = 0; j < 8; j++) acc[i][j] += ar[i] * br[j];
                }
            }
        }

        if (tid < 256) {
            float bias[8];
#pragma unroll
            for (int j = 0; j < 8; j++) bias[j] = __ldg(b_i2h + n0 + tx * 8 + j);
#pragma unroll
            for (int i = 0; i < 8; i++) {
                float4 v0 = make_float4(acc[i][0] + bias[0], acc[i][1] + bias[1],
                                        acc[i][2] + bias[2], acc[i][3] + bias[3]);
                float4 v1 = make_float4(acc[i][4] + bias[4], acc[i][5] + bias[5],
                                        acc[i][6] + bias[6], acc[i][7] + bias[7]);
                float* cp = g_c + (size_t)(m0 + ty * 8 + i) * 1024 + n0 + tx * 8;
                *(float4*)(cp)     = v0;
                *(float4*)(cp + 4) = v1;
            }
        }
        __threadfence();          // make this thread's tile stores visible
        __syncthreads();          // all threads fenced
        if (tid == 0) atomicAdd(&g_cnt[g >> 3], 1);   // chunk counter (8 => ready)
        return;
    }

    // ================= recurrence role (R15 + pipelined poll) =================
    float (*sh)[H] = (float (*)[H])sbuf;          // double-buffered staged h_t

    int b   = bid;
    int w   = tid >> 5;
    int L   = tid & 31;
    int r0  = b * RPB;
    int row = r0 + w;

    // weight registers: 8 float4, k = 4L + 128j
    float4 wv[8];
    {
        const float* wp = W_i2h + (size_t)row * 2048 + 1024 + 4 * L;
#pragma unroll
        for (int j = 0; j < 8; j++) wv[j] = *(const float4*)(wp + 128 * j);
    }

    // warp0 lanes L<16 own publish; gate chunk 0 then coalesced c prefetch
    float cnext = 0.f;
    if (w == 0 && L < RPB) {
        while (ld_acq(&g_cnt[0]) < 8) {}
        cnext = __ldg(g_c + r0 + L);
    }

    const int sbase = 4 * L;

    for (int t = 0; t < T_STEPS; t++) {
        float ccur = cnext;

        // pipelined poll (depth 2): keep two 16B loads in flight; check the
        // older flight while the newer samples the line ~lat/2 later.
        // Sampling period ~130cyc instead of ~260 -> halves the straggler
        // quantization that bar1 max-couples across 64 blocks.
        const unsigned long long* p0 = &g_hp[t & 1][2 * tid];
        unsigned long long a0, b0, a1, b1;
        ld_pair2(p0, a0, b0);     // flight 0 (older)
        ld_pair2(p0, a1, b1);     // flight 1 (newer)
        while (pair_tag(a0) < t || pair_tag(b0) < t) {
            a0 = a1; b0 = b1;     // rotate: newer becomes older
            ld_pair2(p0, a1, b1); // issue next sample
        }
        *(float2*)&sh[t & 1][2 * tid] = make_float2(pair_val(a0), pair_val(b0));
        __syncthreads();   // bar1: h staged

        if (w == 0 && L < RPB && t + 1 < T_STEPS) {
            int tn = t + 1;
            if ((tn & 127) == 0) {                  // entering a new c-chunk
                const int* cp = &g_cnt[tn >> 7];
                while (ld_acq(cp) < 8) {}
            }
            cnext = __ldg(g_c + (size_t)tn * H + r0 + L);
        }

        // dot: full row per warp, 32 k per lane, 4 partial accumulators
        const float* shb = sh[t & 1];
        float a0f = 0.f, a1f = 0.f, a2f = 0.f, a3f = 0.f;
#pragma unroll
        for (int j = 0; j < 8; j += 4) {
            float4 h0 = *(const float4*)&shb[sbase + 128 * (j + 0)];
            float4 h1 = *(const float4*)&shb[sbase + 128 * (j + 1)];
            float4 h2 = *(const float4*)&shb[sbase + 128 * (j + 2)];
            float4 h3 = *(const float4*)&shb[sbase + 128 * (j + 3)];
            a0f += wv[j + 0].x * h0.x + wv[j + 0].y * h0.y + wv[j + 0].z * h0.z + wv[j + 0].w * h0.w;
            a1f += wv[j + 1].x * h1.x + wv[j + 1].y * h1.y + wv[j + 1].z * h1.z + wv[j + 1].w * h1.w;
            a2f += wv[j + 2].x * h2.x + wv[j + 2].y * h2.y + wv[j + 2].z * h2.z + wv[j + 2].w * h2.w;
            a3f += wv[j + 3].x * h3.x + wv[j + 3].y * h3.y + wv[j + 3].z * h3.z + wv[j + 3].w * h3.w;
        }
        float acc = (a0f + a1f) + (a2f + a3f);
#pragma unroll
        for (int off = 16; off > 0; off >>= 1)
            acc += __shfl_down_sync(0xffffffffu, acc, off);
        if (L == 0) sw[w] = acc;
        __syncthreads();   // bar2: row sums ready

        if (w == 0 && L < RPB) {
            float hn = tanh_fast(sw[L] + ccur);
            // coalesced publish: 16 lanes -> one 128B L2 line, tag rides with data
            st_pair(&g_hp[(t + 1) & 1][r0 + L], pack_pair(t + 1, hn));
            if (t == T_STEPS - 1) g_hfin[r0 + L] = hn;
        }
    }
}

// ---------------- output: out[r] = h_T . W_h2o[r] + b_h2o[r] -------------
__global__ void __launch_bounds__(256) out_kernel(const float* __restrict__ W_h2o,
                                                  const float* __restrict__ b_h2o,
                                                  float* __restrict__ out) {
    int r = blockIdx.x * 8 + (threadIdx.x >> 5);
    int lane = threadIdx.x & 31;
    const float* wr = W_h2o + (size_t)r * 1024;
    const float* h  = g_hfin;
    float acc = 0.f;
    for (int k4 = lane; k4 < 256; k4 += 32) {
        float4 wvv = *(const float4*)(wr + k4 * 4);
        float4 hv  = *(const float4*)(h + k4 * 4);
        acc += wvv.x * hv.x + wvv.y * hv.y + wvv.z * hv.z + wvv.w * hv.w;
    }
#pragma unroll
    for (int off = 16; off > 0; off >>= 1)
        acc += __shfl_down_sync(0xffffffffu, acc, off);
    if (lane == 0) out[r] = acc + __ldg(b_h2o + r);
}

// ---------------- launch (5 launches: fused sits in ncu capture slot) ----
extern "C" void kernel_launch(void* const* d_in, const int* in_sizes, int n_in,
                              void* d_out, int out_size) {
    const float* x      = (const float*)d_in[0];
    const float* W_i2h  = (const float*)d_in[1];
    const float* b_i2h  = (const float*)d_in[2];
    const float* W_h2o  = (const float*)d_in[3];
    const float* b_h2o  = (const float*)d_in[4];
    float* out = (float*)d_out;

    init_a<<<2, 512>>>();
    init_b<<<2, 512>>>();
    init_c<<<1, 256>>>();
    rnn_fused<<<NB + NGB, NT>>>(x, W_i2h, b_i2h);
    out_kernel<<<H / 8, 256>>>(W_h2o, b_h2o, out);
}